// round 12
// baseline (speedup 1.0000x reference)
#include <cuda_runtime.h>
#include <cuda_bf16.h>
#include <stdint.h>
#include <math.h>

typedef uint32_t u32;
typedef uint64_t u64;

static constexpr int THREADS = 256;
static constexpr int MT      = 128;     // points per CTA
static constexpr float OMEGA = 30.0f;
static constexpr int NSUB    = 52;      // 26 units x (hi,lo) 32KB subunits
static constexpr int SUB_BYTES = 32768;

// ---- shared memory layout (bytes) ----
static constexpr int RING_OFF  = 0;            // 3 x 32KB weight ring
static constexpr int FFRAG_OFF = 98304;        // ff fragments: 8 warps x 16KB = 128KB
static constexpr int BOW_OFF   = 229376;       // B (256 f) + out_w (128 f)
static constexpr int MBAR_OFF  = 230912;       // full[3] + empty[3]
static constexpr int SMEM_BYTES = 231424;

// weight blob: 52 subunits x 32KB, execution order, bf16 [n][k] swizzled
__device__ __align__(16) unsigned char g_wblob[(size_t)NSUB * SUB_BYTES];
// precombined bias for epilogue2: b2[l] (+ skb[l/2] on even l)
__device__ __align__(16) float g_b2c[8 * 128];

// ============================ PTX helpers ============================

__device__ __forceinline__ u32 smem_u32(const void* p) {
    return (u32)__cvta_generic_to_shared(p);
}

#define MBARRIER_INIT(addr, cnt) \
    asm volatile("mbarrier.init.shared.b64 [%0], %1;" :: "r"(addr), "r"((u32)(cnt)) : "memory")
#define MBARRIER_EXPECT_TX(addr, b) \
    asm volatile("mbarrier.arrive.expect_tx.shared.b64 _, [%0], %1;" :: "r"(addr), "r"((u32)(b)) : "memory")
#define MBARRIER_ARRIVE(addr) \
    asm volatile("mbarrier.arrive.shared.b64 _, [%0];" :: "r"(addr) : "memory")

#define MBARRIER_WAIT_PARITY(mbar_smem_addr, phase_parity) do { \
    u32 _mbar = (u32)(mbar_smem_addr); \
    u32 _parity = (u32)(phase_parity); \
    u32 _done; \
    asm volatile( \
        "{\n\t.reg .pred p;\n\t" \
        "mbarrier.try_wait.parity.acquire.cta.shared::cta.b64 p, [%1], %2;\n\t" \
        "selp.b32 %0, 1, 0, p;\n\t}" \
        : "=r"(_done) : "r"(_mbar), "r"(_parity) : "memory"); \
    if (!_done) { \
        asm volatile( \
            "{\n\t.reg .pred P1;\n\t" \
            "WAIT_LOOP_%=:\n\t" \
            "mbarrier.try_wait.parity.acquire.cta.shared::cta.b64 P1, [%0], %1, 0x989680;\n\t" \
            "@P1 bra.uni WAIT_DONE_%=;\n\t" \
            "bra.uni WAIT_LOOP_%=;\n\t" \
            "WAIT_DONE_%=:\n\t}" \
            :: "r"(_mbar), "r"(_parity) : "memory"); \
    } \
} while (0)

// Relaxed wait: post-wait SMEM access is async-proxy only (cp.async.bulk).
#define MBARRIER_WAIT_PARITY_RELAXED(mbar_smem_addr, phase_parity) do { \
    u32 _mbar = (u32)(mbar_smem_addr); \
    u32 _parity = (u32)(phase_parity); \
    u32 _done; \
    asm volatile( \
        "{\n\t.reg .pred p;\n\t" \
        "mbarrier.try_wait.parity.relaxed.cta.shared::cta.b64 p, [%1], %2, 0x989680;\n\t" \
        "selp.b32 %0, 1, 0, p;\n\t}" \
        : "=r"(_done) : "r"(_mbar), "r"(_parity) : "memory"); \
    if (!_done) { \
        asm volatile( \
            "{\n\t.reg .pred P1;\n\t" \
            "WAIT_LOOP_%=:\n\t" \
            "mbarrier.try_wait.parity.relaxed.cta.shared::cta.b64 P1, [%0], %1, 0x989680;\n\t" \
            "@P1 bra.uni WAIT_DONE_%=;\n\t" \
            "bra.uni WAIT_LOOP_%=;\n\t" \
            "WAIT_DONE_%=:\n\t}" \
            :: "r"(_mbar), "r"(_parity) : "memory"); \
    } \
} while (0)

__device__ __forceinline__ void bulk_copy(u32 dst, const void* src, u32 bytes, u32 mbar) {
    asm volatile(
        "cp.async.bulk.shared::cluster.global.mbarrier::complete_tx::bytes [%0], [%1], %2, [%3];"
        :: "r"(dst), "l"(src), "r"(bytes), "r"(mbar) : "memory");
}

__device__ __forceinline__ void ldsm4(u32& r0, u32& r1, u32& r2, u32& r3, u32 addr) {
    asm volatile("ldmatrix.sync.aligned.m8n8.x4.shared.b16 {%0,%1,%2,%3}, [%4];"
                 : "=r"(r0), "=r"(r1), "=r"(r2), "=r"(r3) : "r"(addr));
}

__device__ __forceinline__ void mma16816(float (&d)[4], const u32 (&a)[4], u32 b0, u32 b1) {
    asm volatile(
        "mma.sync.aligned.m16n8k16.row.col.f32.bf16.bf16.f32 "
        "{%0,%1,%2,%3},{%4,%5,%6,%7},{%8,%9},{%0,%1,%2,%3};"
        : "+f"(d[0]), "+f"(d[1]), "+f"(d[2]), "+f"(d[3])
        : "r"(a[0]), "r"(a[1]), "r"(a[2]), "r"(a[3]), "r"(b0), "r"(b1));
}

// bf16 -> f32 is exactly bits<<16 (cheap ALU, no CVT)
__device__ __forceinline__ float bflo(u32 v) {
    return __uint_as_float(v << 16);
}
__device__ __forceinline__ float bfhi(u32 v) {
    return __uint_as_float(v & 0xFFFF0000u);
}

// split v0,v1 into packed bf16 hi + packed bf16 lo (residual), 1 CVT each way
__device__ __forceinline__ void bf_split2(float v0, float v1, u32& hi, u32& lo) {
    asm("cvt.rn.bf16x2.f32 %0, %1, %2;" : "=r"(hi) : "f"(v1), "f"(v0));
    float r0 = v0 - bflo(hi);
    float r1 = v1 - bfhi(hi);
    asm("cvt.rn.bf16x2.f32 %0, %1, %2;" : "=r"(lo) : "f"(r1), "f"(r0));
}

// ---- fast transcendentals (err ~1e-6, far below bf16-split noise) ----
__device__ __forceinline__ float fast_sin(float x) {
    float k = rintf(x * 0.15915494309189535f);
    float r = fmaf(k, -6.28125f, x);            // 6.28125 exact in fp32
    r = fmaf(k, -1.9353071795864769e-3f, r);    // 2*pi = 6.28125 + this
    float s;
    asm("sin.approx.f32 %0, %1;" : "=f"(s) : "f"(r));
    return s;
}
__device__ __forceinline__ float fast_cos(float x) {
    float k = rintf(x * 0.15915494309189535f);
    float r = fmaf(k, -6.28125f, x);
    r = fmaf(k, -1.9353071795864769e-3f, r);
    float c;
    asm("cos.approx.f32 %0, %1;" : "=f"(c) : "f"(r));
    return c;
}
__device__ __forceinline__ float fast_tanh(float x) {
    float e;
    asm("ex2.approx.f32 %0, %1;" : "=f"(e) : "f"(x * 2.8853900817779268f)); // exp(2x)
    float r;
    asm("rcp.approx.f32 %0, %1;" : "=f"(r) : "f"(e + 1.0f));
    return fmaf(-2.0f, r, 1.0f);   // 1 - 2/(e^{2x}+1)
}

// ==================== weight conversion pre-kernel ====================
// Unit order: in_w k0-127, in_w k128-255, then per layer l: w1_l, w2_l,
// (+ skw[l/2] k-chunk0, chunk1 when l even). Element (n,k) = W[k][n].
// In-tile layout: row n = 256B (128 bf16 of k), byte = n*256 + (2k ^ ((n&7)<<4)).
// Also fills g_b2c[l][c] = b2[l][c] + (l even ? skb[l/2][c] : 0).
__global__ void convert_weights(const float* __restrict__ in_w,
                                const float* __restrict__ w1,
                                const float* __restrict__ w2,
                                const float* __restrict__ skw,
                                const float* __restrict__ b2,
                                const float* __restrict__ skb) {
    int gid = blockIdx.x * blockDim.x + threadIdx.x;
    if (gid >= 26 * 16384) return;

    if (gid < 8 * 128) {
        int l = gid >> 7, c = gid & 127;
        float v = b2[l * 128 + c];
        if ((l & 1) == 0) v += skb[(l >> 1) * 128 + c];
        g_b2c[gid] = v;
    }

    int u = gid >> 14, e = gid & 16383;
    int n = e >> 7, k = e & 127;

    float v;
    if (u < 2) {
        v = in_w[(k + u * 128) * 128 + n];
    } else {
        int r = u - 2, l = 0;
        while (true) {
            int len = ((l & 1) == 0) ? 4 : 2;
            if (r < len) break;
            r -= len; l++;
        }
        if (r == 0)      v = w1[l * 16384 + k * 128 + n];
        else if (r == 1) v = w2[l * 16384 + k * 128 + n];
        else             v = skw[(l >> 1) * 32768 + (k + (r - 2) * 128) * 128 + n];
    }

    __nv_bfloat16 hi = __float2bfloat16_rn(v);
    float rem = v - __bfloat162float(hi);
    __nv_bfloat16 lo = __float2bfloat16_rn(rem);

    u32 off = (u32)(n * 256 + ((2 * k) ^ ((n & 7) << 4)));
    size_t base = (size_t)u * 65536;
    *(__nv_bfloat16*)(g_wblob + base + off)         = hi;
    *(__nv_bfloat16*)(g_wblob + base + 32768 + off) = lo;
}

// ==================== GEMM subunit helpers ====================
// Warp tile: m16 x n128 (16 ntiles). A row-major m16k16 frags, B = Wt[n][k]
// (col-major K x N), loaded via ldmatrix.x4 (2 ntiles x 1 kstep per ldsm).

__device__ __forceinline__ void gemm_x(u32 wbase, const u32 (&ah)[8][4], const u32 (&al)[8][4],
                                       bool isHi, float (&d)[16][4], int lane) {
    const u32 off0 = (u32)((((lane & 7) + ((lane >> 4) << 3))) * 256);
    const u32 swz  = (u32)((lane & 7) << 4);
    const u32 kh   = (u32)(((lane >> 3) & 1) * 16);
#pragma unroll
    for (int s = 0; s < 8; s++) {
#pragma unroll
        for (int ntp = 0; ntp < 8; ntp++) {
            u32 r0, r1, r2, r3;
            ldsm4(r0, r1, r2, r3, wbase + off0 + (u32)(ntp * 4096) + (((u32)(32 * s) + kh) ^ swz));
            mma16816(d[2 * ntp],     ah[s], r0, r1);
            mma16816(d[2 * ntp + 1], ah[s], r2, r3);
            if (isHi) {
                mma16816(d[2 * ntp],     al[s], r0, r1);
                mma16816(d[2 * ntp + 1], al[s], r2, r3);
            }
        }
    }
}

__device__ __forceinline__ void gemm_ff(u32 wbase, const char* fr, int kbase,
                                        bool isHi, float (&d)[16][4], int lane) {
    const u32 off0 = (u32)((((lane & 7) + ((lane >> 4) << 3))) * 256);
    const u32 swz  = (u32)((lane & 7) << 4);
    const u32 kh   = (u32)(((lane >> 3) & 1) * 16);
#pragma unroll
    for (int s = 0; s < 8; s++) {
        const int4 q0 = *(const int4*)(fr + ((kbase + s) * 2 + 0) * 512);
        const int4 q1 = *(const int4*)(fr + ((kbase + s) * 2 + 1) * 512);
        u32 ah[4] = {(u32)q0.x, (u32)q1.x, (u32)q0.y, (u32)q1.y};
        u32 al[4] = {(u32)q0.z, (u32)q1.z, (u32)q0.w, (u32)q1.w};
#pragma unroll
        for (int ntp = 0; ntp < 8; ntp++) {
            u32 r0, r1, r2, r3;
            ldsm4(r0, r1, r2, r3, wbase + off0 + (u32)(ntp * 4096) + (((u32)(32 * s) + kh) ^ swz));
            mma16816(d[2 * ntp],     ah, r0, r1);
            mma16816(d[2 * ntp + 1], ah, r2, r3);
            if (isHi) {
                mma16816(d[2 * ntp],     al, r0, r1);
                mma16816(d[2 * ntp + 1], al, r2, r3);
            }
        }
    }
}

// per-ntile-pair epilogue, EMODE: 0 = input sin, 1 = tanh -> h, 2 = x residual update
template<int EMODE>
__device__ __forceinline__ void epi_nt(int s, int qc, const float* __restrict__ bias,
                                       float (&d)[16][4], u32 (*oh)[4], u32 (*ol)[4]) {
#pragma unroll
    for (int p = 0; p < 2; p++) {
        int nt = 2 * s + p;
        int col = 8 * nt + 2 * qc;
        float2 bb = *(const float2*)(bias + col);
        int i0 = 2 * p, i1 = 2 * p + 1;
        float v00, v01, v10, v11;
        if (EMODE == 0) {
            v00 = fast_sin(OMEGA * (d[nt][0] + bb.x));
            v01 = fast_sin(OMEGA * (d[nt][1] + bb.y));
            v10 = fast_sin(OMEGA * (d[nt][2] + bb.x));
            v11 = fast_sin(OMEGA * (d[nt][3] + bb.y));
        } else if (EMODE == 1) {
            v00 = fast_tanh(d[nt][0] + bb.x);
            v01 = fast_tanh(d[nt][1] + bb.y);
            v10 = fast_tanh(d[nt][2] + bb.x);
            v11 = fast_tanh(d[nt][3] + bb.y);
        } else {
            v00 = bflo(oh[s][i0]) + bflo(ol[s][i0]) + d[nt][0] + bb.x;
            v01 = bfhi(oh[s][i0]) + bfhi(ol[s][i0]) + d[nt][1] + bb.y;
            v10 = bflo(oh[s][i1]) + bflo(ol[s][i1]) + d[nt][2] + bb.x;
            v11 = bfhi(oh[s][i1]) + bfhi(ol[s][i1]) + d[nt][3] + bb.y;
        }
        bf_split2(v00, v01, oh[s][i0], ol[s][i0]);
        bf_split2(v10, v11, oh[s][i1], ol[s][i1]);
    }
}

// Fused final (lo-term) sub: ntp-outer MMA issue with the epilogue of ntp-1
// interleaved, so the warp keeps feeding the tensor pipe through its own
// epilogue. mbarrier arrive fires right after the last MMA issue.
template<int EMODE, bool FF>
__device__ __forceinline__ void gemm_lo_fused(u32 wbase, const u32 (*asrc)[4],
                                              const char* fr, int kbase,
                                              float (&d)[16][4], int lane, int qc,
                                              const float* __restrict__ bias,
                                              u32 (*oh)[4], u32 (*ol)[4],
                                              u32 mbe_addr) {
    const u32 off0 = (u32)((((lane & 7) + ((lane >> 4) << 3))) * 256);
    const u32 swz  = (u32)((lane & 7) << 4);
    const u32 kh   = (u32)(((lane >> 3) & 1) * 16);

    u32 areg[8][4];
    if (FF) {
#pragma unroll
        for (int s = 0; s < 8; s++) {
            const int4 q0 = *(const int4*)(fr + ((kbase + s) * 2 + 0) * 512);
            const int4 q1 = *(const int4*)(fr + ((kbase + s) * 2 + 1) * 512);
            areg[s][0] = (u32)q0.x; areg[s][1] = (u32)q1.x;
            areg[s][2] = (u32)q0.y; areg[s][3] = (u32)q1.y;
        }
    }
    const u32 (*ap)[4] = FF ? (const u32(*)[4])areg : asrc;

#pragma unroll
    for (int ntp = 0; ntp < 8; ntp++) {
#pragma unroll
        for (int s = 0; s < 8; s++) {
            u32 aa[4] = {ap[s][0], ap[s][1], ap[s][2], ap[s][3]};
            u32 r0, r1, r2, r3;
            ldsm4(r0, r1, r2, r3, wbase + off0 + (u32)(ntp * 4096) + (((u32)(32 * s) + kh) ^ swz));
            mma16816(d[2 * ntp],     aa, r0, r1);
            mma16816(d[2 * ntp + 1], aa, r2, r3);
        }
        if (ntp == 7 && lane == 0) MBARRIER_ARRIVE(mbe_addr);
        if (ntp > 0) epi_nt<EMODE>(ntp - 1, qc, bias, d, oh, ol);
    }
    epi_nt<EMODE>(7, qc, bias, d, oh, ol);
}

__device__ __forceinline__ void zero_d(float (&d)[16][4]) {
#pragma unroll
    for (int i = 0; i < 16; i++)
#pragma unroll
        for (int j = 0; j < 4; j++) d[i][j] = 0.0f;
}

__device__ __forceinline__ void prefetch_sub(u32 ring, u32 mbf, int sub) {
    u32 mb = mbf + 8 * (sub % 3);
    MBARRIER_EXPECT_TX(mb, SUB_BYTES);
    bulk_copy(ring + (sub % 3) * SUB_BYTES, g_wblob + (size_t)sub * SUB_BYTES, SUB_BYTES, mb);
}

// ==================== main kernel ====================

extern __shared__ __align__(16) char smem[];

__global__ void __launch_bounds__(THREADS, 1)
pinn_mma(const float* __restrict__ S,  const float* __restrict__ Tt,
         const float* __restrict__ Bm,
         const float* __restrict__ in_b, const float* __restrict__ b1,
         const float* __restrict__ ow,   const float* __restrict__ ob,
         float* __restrict__ out, int N)
{
    const int tid  = threadIdx.x;
    const int warp = tid >> 5, lane = tid & 31;
    const int grp  = lane >> 2, qc = lane & 3;
    const int base = blockIdx.x * MT;

    const u32 sb   = smem_u32(smem);
    const u32 ring = sb + RING_OFF;
    const u32 mbf  = sb + MBAR_OFF;        // full[3] at +0,8,16
    const u32 mbe  = sb + MBAR_OFF + 24;   // empty[3] at +24,32,40
    float* Bs  = (float*)(smem + BOW_OFF);      // 256 floats
    float* ows = Bs + 256;                      // 128 floats
    char*  fr  = smem + FFRAG_OFF + warp * 16384 + lane * 16;  // this thread's frag base

    if (tid == 0) {
        MBARRIER_INIT(mbf + 0,  1);
        MBARRIER_INIT(mbf + 8,  1);
        MBARRIER_INIT(mbf + 16, 1);
        MBARRIER_INIT(mbe + 0,  8);
        MBARRIER_INIT(mbe + 8,  8);
        MBARRIER_INIT(mbe + 16, 8);
    }
    __syncthreads();   // barrier init visible before any wait/expect/arrive below

    if (tid == 0) {
        prefetch_sub(ring, mbf, 0);
        prefetch_sub(ring, mbf, 1);
        prefetch_sub(ring, mbf, 2);
    }

    // stage B and out_w
    if (tid < 256) Bs[tid] = Bm[tid];
    if (tid < 128) ows[tid] = ow[tid];

    // this thread's two point rows
    const int r0g = base + warp * 16 + grp;
    const int r1g = r0g + 8;
    const float s0 = (r0g < N) ? S[r0g]  : 0.0f;
    const float t0 = (r0g < N) ? Tt[r0g] : 0.0f;
    const float s1 = (r1g < N) ? S[r1g]  : 0.0f;
    const float t1 = (r1g < N) ? Tt[r1g] : 0.0f;
    __syncthreads();

    // ---- Fourier-feature A fragments -> per-warp smem (overlaps weight copies) ----
    // A[m][k]: k<128 sin(proj[f=k]); k>=128 cos(proj[f=k-128]).
    // kstep t (sin) / t+8 (cos); within kstep, this thread needs f = 16t + {2qc,2qc+1,2qc+8,2qc+9}.
#pragma unroll
    for (int t = 0; t < 8; t++) {
        int f0 = 16 * t + 2 * qc;
        float sn[2][4], cs[2][4];
#pragma unroll
        for (int j = 0; j < 4; j++) {
            int f = f0 + ((j & 1) ? 1 : 0) + ((j & 2) ? 8 : 0);
            float p0 = s0 * Bs[f] + t0 * Bs[128 + f];
            float p1 = s1 * Bs[f] + t1 * Bs[128 + f];
            sn[0][j] = fast_sin(p0);  cs[0][j] = fast_cos(p0);
            sn[1][j] = fast_sin(p1);  cs[1][j] = fast_cos(p1);
        }
        u32 h0, l0, h1, l1, h2, l2, h3, l3;
        // sin -> kstep t
        bf_split2(sn[0][0], sn[0][1], h0, l0);   // a0: row grp,  f0,f0+1
        bf_split2(sn[1][0], sn[1][1], h1, l1);   // a1: row grp+8
        bf_split2(sn[0][2], sn[0][3], h2, l2);   // a2: row grp,  f0+8,f0+9
        bf_split2(sn[1][2], sn[1][3], h3, l3);   // a3
        *(int4*)(fr + (t * 2 + 0) * 512) = make_int4((int)h0, (int)h2, (int)l0, (int)l2);
        *(int4*)(fr + (t * 2 + 1) * 512) = make_int4((int)h1, (int)h3, (int)l1, (int)l3);
        // cos -> kstep t+8
        bf_split2(cs[0][0], cs[0][1], h0, l0);
        bf_split2(cs[1][0], cs[1][1], h1, l1);
        bf_split2(cs[0][2], cs[0][3], h2, l2);
        bf_split2(cs[1][2], cs[1][3], h3, l3);
        *(int4*)(fr + ((t + 8) * 2 + 0) * 512) = make_int4((int)h0, (int)h2, (int)l0, (int)l2);
        *(int4*)(fr + ((t + 8) * 2 + 1) * 512) = make_int4((int)h1, (int)h3, (int)l1, (int)l3);
    }
    // (no sync needed: each thread reads back only its own records)

    // ---- phase stagger: delay warps 4-7 (~epilogue length) so each SMSP's two
    // warps run anti-phase; producer (warp 0) stays early so refills issue
    // immediately when the late warps arrive on empty ----
    if (warp >= 4) {
        u32 c0; asm volatile("mov.u32 %0, %%clock;" : "=r"(c0));
        u32 el = 0;
        do { u32 c; asm volatile("mov.u32 %0, %%clock;" : "=r"(c)); el = c - c0; } while (el < 2600u);
    }

    int sub = 0;
    float d[16][4];
    u32 xh[8][4], xl[8][4];

    // Per-sub protocol (no CTA barriers => warps can skew by up to 2 subs):
    //  - each warp: wait full(sub) [acquire], gemm, lane0 arrives on empty(sub)
    //  - tid0 additionally: relaxed-wait empty(sub) round complete, refill sub+3
#define DO_SUB(GEMM_CALL) do { \
        MBARRIER_WAIT_PARITY(mbf + 8 * (sub % 3), (sub / 3) & 1); \
        GEMM_CALL; \
        if (lane == 0) MBARRIER_ARRIVE(mbe + 8 * (sub % 3)); \
        if (tid == 0 && sub + 3 < NSUB) { \
            MBARRIER_WAIT_PARITY_RELAXED(mbe + 8 * (sub % 3), (sub / 3) & 1); \
            prefetch_sub(ring, mbf, sub + 3); \
        } \
        sub++; \
    } while (0)

#define DO_FF(kbase, isHi) \
    DO_SUB(gemm_ff(ring + (u32)((sub % 3) * SUB_BYTES), fr, (kbase), (isHi), d, lane))
#define DO_X(AH, AL, isHi) \
    DO_SUB(gemm_x(ring + (u32)((sub % 3) * SUB_BYTES), (AH), (AL), (isHi), d, lane))

// Fused final sub of a GEMM group: MMA + interleaved epilogue (arrive inside).
#define DO_FUSED(EMODE, FFFLAG, ASRC, KB, BIAS, OH, OL) do { \
        MBARRIER_WAIT_PARITY(mbf + 8 * (sub % 3), (sub / 3) & 1); \
        gemm_lo_fused<EMODE, FFFLAG>(ring + (u32)((sub % 3) * SUB_BYTES), \
            (const u32(*)[4])(ASRC), fr, (KB), d, lane, qc, (BIAS), (OH), (OL), \
            mbe + 8 * (sub % 3)); \
        if (tid == 0 && sub + 3 < NSUB) { \
            MBARRIER_WAIT_PARITY_RELAXED(mbe + 8 * (sub % 3), (sub / 3) & 1); \
            prefetch_sub(ring, mbf, sub + 3); \
        } \
        sub++; \
    } while (0)

    // ---- input layer: D = ff @ in_w (K=256), x = sin(OMEGA*(D + in_b)) ----
    zero_d(d);
    DO_FF(0, true);  DO_FF(0, false);
    DO_FF(8, true);
    DO_FUSED(0, true, xh /*dummy*/, 8, in_b, xh, xl);

    // ---- residual blocks ----
    for (int l = 0; l < 8; l++) {
        const bool skip = ((l & 1) == 0);
        u32 hh[8][4], hl[8][4];

        // GEMM1: D = x @ w1_l ; h = tanh(D + b1_l) fused into lo-sub
        zero_d(d);
        DO_X(xh, xl, true);
        DO_FUSED(1, false, xh, 0, b1 + l * 128, hh, hl);

        // GEMM2: D = h @ w2_l (+ ff @ skip_w[l/2]); x-update fused into final sub
        zero_d(d);
        DO_X(hh, hl, true);
        if (skip) {
            DO_X(hh, hl, false);
            DO_FF(0, true);  DO_FF(0, false);
            DO_FF(8, true);
            DO_FUSED(2, true, xh /*dummy*/, 8, g_b2c + l * 128, xh, xl);
        } else {
            DO_FUSED(2, false, hh, 0, g_b2c + l * 128, xh, xl);
        }
    }

    // ---- output layer: out = x @ out_w + out_b ----
    float a0 = 0.0f, a1 = 0.0f;
#pragma unroll
    for (int s = 0; s < 8; s++) {
#pragma unroll
        for (int p = 0; p < 2; p++) {
            int nt = 2 * s + p;
            int col = 8 * nt + 2 * qc;
            float w0 = ows[col], w1v = ows[col + 1];
            int i0 = 2 * p, i1 = 2 * p + 1;
            a0 += (bflo(xh[s][i0]) + bflo(xl[s][i0])) * w0
                + (bfhi(xh[s][i0]) + bfhi(xl[s][i0])) * w1v;
            a1 += (bflo(xh[s][i1]) + bflo(xl[s][i1])) * w0
                + (bfhi(xh[s][i1]) + bfhi(xl[s][i1])) * w1v;
        }
    }
    a0 += __shfl_xor_sync(0xFFFFFFFF, a0, 1);
    a0 += __shfl_xor_sync(0xFFFFFFFF, a0, 2);
    a1 += __shfl_xor_sync(0xFFFFFFFF, a1, 1);
    a1 += __shfl_xor_sync(0xFFFFFFFF, a1, 2);
    if (qc == 0) {
        float obv = ob[0];
        if (r0g < N) out[r0g] = a0 + obv;
        if (r1g < N) out[r1g] = a1 + obv;
    }
#undef DO_FF
#undef DO_X
#undef DO_SUB
#undef DO_FUSED
}

// ==================== launcher ====================

extern "C" void kernel_launch(void* const* d_in, const int* in_sizes, int n_in,
                              void* d_out, int out_size) {
    const float* S    = (const float*)d_in[0];
    const float* T    = (const float*)d_in[1];
    const float* B    = (const float*)d_in[2];
    const float* in_w = (const float*)d_in[3];
    const float* in_b = (const float*)d_in[4];
    const float* w1   = (const float*)d_in[5];
    const float* b1   = (const float*)d_in[6];
    const float* w2   = (const float*)d_in[7];
    const float* b2   = (const float*)d_in[8];
    const float* skw  = (const float*)d_in[9];
    const float* skb  = (const float*)d_in[10];
    const float* ow   = (const float*)d_in[11];
    const float* ob   = (const float*)d_in[12];
    float* out        = (float*)d_out;

    int N = in_sizes[0];

    convert_weights<<<(26 * 16384 + 255) / 256, 256>>>(in_w, w1, w2, skw, b2, skb);

    cudaFuncSetAttribute(pinn_mma, cudaFuncAttributeMaxDynamicSharedMemorySize, SMEM_BYTES);
    int grid = (N + MT - 1) / MT;
    pinn_mma<<<grid, THREADS, SMEM_BYTES>>>(S, T, B, in_b, b1, ow, ob, out, N);
}

// round 13
// speedup vs baseline: 1.0265x; 1.0265x over previous
#include <cuda_runtime.h>
#include <cuda_bf16.h>
#include <stdint.h>
#include <math.h>

typedef uint32_t u32;
typedef uint64_t u64;

static constexpr int THREADS = 256;
static constexpr int MT      = 128;     // points per CTA
static constexpr float OMEGA = 30.0f;
static constexpr int NSUB    = 52;      // 26 units x (hi,lo) 32KB subunits
static constexpr int SUB_BYTES = 32768;

// ---- shared memory layout (bytes) ----
static constexpr int RING_OFF  = 0;            // 3 x 32KB weight ring
static constexpr int FFRAG_OFF = 98304;        // ff fragments: 8 warps x 16KB = 128KB
static constexpr int BOW_OFF   = 229376;       // B (256 f) + out_w (128 f)
static constexpr int MBAR_OFF  = 230912;       // full[3] + cnt[3]
static constexpr int SMEM_BYTES = 231424;

// weight blob: 52 subunits x 32KB, execution order, bf16 [n][k] swizzled
__device__ __align__(16) unsigned char g_wblob[(size_t)NSUB * SUB_BYTES];
// precombined bias for epilogue2: b2[l] (+ skb[l/2] on even l)
__device__ __align__(16) float g_b2c[8 * 128];

// ============================ PTX helpers ============================

__device__ __forceinline__ u32 smem_u32(const void* p) {
    return (u32)__cvta_generic_to_shared(p);
}

#define MBARRIER_INIT(addr, cnt) \
    asm volatile("mbarrier.init.shared.b64 [%0], %1;" :: "r"(addr), "r"((u32)(cnt)) : "memory")
#define MBARRIER_EXPECT_TX(addr, b) \
    asm volatile("mbarrier.arrive.expect_tx.shared.b64 _, [%0], %1;" :: "r"(addr), "r"((u32)(b)) : "memory")

#define MBARRIER_WAIT_PARITY(mbar_smem_addr, phase_parity) do { \
    u32 _mbar = (u32)(mbar_smem_addr); \
    u32 _parity = (u32)(phase_parity); \
    u32 _done; \
    asm volatile( \
        "{\n\t.reg .pred p;\n\t" \
        "mbarrier.try_wait.parity.acquire.cta.shared::cta.b64 p, [%1], %2;\n\t" \
        "selp.b32 %0, 1, 0, p;\n\t}" \
        : "=r"(_done) : "r"(_mbar), "r"(_parity) : "memory"); \
    if (!_done) { \
        asm volatile( \
            "{\n\t.reg .pred P1;\n\t" \
            "WAIT_LOOP_%=:\n\t" \
            "mbarrier.try_wait.parity.acquire.cta.shared::cta.b64 P1, [%0], %1, 0x989680;\n\t" \
            "@P1 bra.uni WAIT_DONE_%=;\n\t" \
            "bra.uni WAIT_LOOP_%=;\n\t" \
            "WAIT_DONE_%=:\n\t}" \
            :: "r"(_mbar), "r"(_parity) : "memory"); \
    } \
} while (0)

__device__ __forceinline__ void bulk_copy(u32 dst, const void* src, u32 bytes, u32 mbar) {
    asm volatile(
        "cp.async.bulk.shared::cluster.global.mbarrier::complete_tx::bytes [%0], [%1], %2, [%3];"
        :: "r"(dst), "l"(src), "r"(bytes), "r"(mbar) : "memory");
}

__device__ __forceinline__ void ldsm4(u32& r0, u32& r1, u32& r2, u32& r3, u32 addr) {
    asm volatile("ldmatrix.sync.aligned.m8n8.x4.shared.b16 {%0,%1,%2,%3}, [%4];"
                 : "=r"(r0), "=r"(r1), "=r"(r2), "=r"(r3) : "r"(addr));
}

__device__ __forceinline__ void mma16816(float (&d)[4], const u32 (&a)[4], u32 b0, u32 b1) {
    asm volatile(
        "mma.sync.aligned.m16n8k16.row.col.f32.bf16.bf16.f32 "
        "{%0,%1,%2,%3},{%4,%5,%6,%7},{%8,%9},{%0,%1,%2,%3};"
        : "+f"(d[0]), "+f"(d[1]), "+f"(d[2]), "+f"(d[3])
        : "r"(a[0]), "r"(a[1]), "r"(a[2]), "r"(a[3]), "r"(b0), "r"(b1));
}

// bf16 -> f32 is exactly bits<<16 (cheap ALU, no CVT)
__device__ __forceinline__ float bflo(u32 v) {
    return __uint_as_float(v << 16);
}
__device__ __forceinline__ float bfhi(u32 v) {
    return __uint_as_float(v & 0xFFFF0000u);
}

// split v0,v1 into packed bf16 hi + packed bf16 lo (residual), 1 CVT each way
__device__ __forceinline__ void bf_split2(float v0, float v1, u32& hi, u32& lo) {
    asm("cvt.rn.bf16x2.f32 %0, %1, %2;" : "=r"(hi) : "f"(v1), "f"(v0));
    float r0 = v0 - bflo(hi);
    float r1 = v1 - bfhi(hi);
    asm("cvt.rn.bf16x2.f32 %0, %1, %2;" : "=r"(lo) : "f"(r1), "f"(r0));
}

// ---- fast transcendentals (err ~1e-6, far below bf16-split noise) ----
__device__ __forceinline__ float fast_sin(float x) {
    float k = rintf(x * 0.15915494309189535f);
    float r = fmaf(k, -6.28125f, x);            // 6.28125 exact in fp32
    r = fmaf(k, -1.9353071795864769e-3f, r);    // 2*pi = 6.28125 + this
    float s;
    asm("sin.approx.f32 %0, %1;" : "=f"(s) : "f"(r));
    return s;
}
__device__ __forceinline__ float fast_cos(float x) {
    float k = rintf(x * 0.15915494309189535f);
    float r = fmaf(k, -6.28125f, x);
    r = fmaf(k, -1.9353071795864769e-3f, r);
    float c;
    asm("cos.approx.f32 %0, %1;" : "=f"(c) : "f"(r));
    return c;
}
__device__ __forceinline__ float fast_tanh(float x) {
    float e;
    asm("ex2.approx.f32 %0, %1;" : "=f"(e) : "f"(x * 2.8853900817779268f)); // exp(2x)
    float r;
    asm("rcp.approx.f32 %0, %1;" : "=f"(r) : "f"(e + 1.0f));
    return fmaf(-2.0f, r, 1.0f);   // 1 - 2/(e^{2x}+1)
}

// ==================== weight conversion pre-kernel ====================
// Unit order: in_w k0-127, in_w k128-255, then per layer l: w1_l, w2_l,
// (+ skw[l/2] k-chunk0, chunk1 when l even). Element (n,k) = W[k][n].
// In-tile layout: row n = 256B (128 bf16 of k), byte = n*256 + (2k ^ ((n&7)<<4)).
// Also fills g_b2c[l][c] = b2[l][c] + (l even ? skb[l/2][c] : 0).
__global__ void convert_weights(const float* __restrict__ in_w,
                                const float* __restrict__ w1,
                                const float* __restrict__ w2,
                                const float* __restrict__ skw,
                                const float* __restrict__ b2,
                                const float* __restrict__ skb) {
    int gid = blockIdx.x * blockDim.x + threadIdx.x;
    if (gid >= 26 * 16384) return;

    if (gid < 8 * 128) {
        int l = gid >> 7, c = gid & 127;
        float v = b2[l * 128 + c];
        if ((l & 1) == 0) v += skb[(l >> 1) * 128 + c];
        g_b2c[gid] = v;
    }

    int u = gid >> 14, e = gid & 16383;
    int n = e >> 7, k = e & 127;

    float v;
    if (u < 2) {
        v = in_w[(k + u * 128) * 128 + n];
    } else {
        int r = u - 2, l = 0;
        while (true) {
            int len = ((l & 1) == 0) ? 4 : 2;
            if (r < len) break;
            r -= len; l++;
        }
        if (r == 0)      v = w1[l * 16384 + k * 128 + n];
        else if (r == 1) v = w2[l * 16384 + k * 128 + n];
        else             v = skw[(l >> 1) * 32768 + (k + (r - 2) * 128) * 128 + n];
    }

    __nv_bfloat16 hi = __float2bfloat16_rn(v);
    float rem = v - __bfloat162float(hi);
    __nv_bfloat16 lo = __float2bfloat16_rn(rem);

    u32 off = (u32)(n * 256 + ((2 * k) ^ ((n & 7) << 4)));
    size_t base = (size_t)u * 65536;
    *(__nv_bfloat16*)(g_wblob + base + off)         = hi;
    *(__nv_bfloat16*)(g_wblob + base + 32768 + off) = lo;
}

// ==================== GEMM subunit helpers ====================
// Warp tile: m16 x n128 (16 ntiles). A row-major m16k16 frags, B = Wt[n][k]
// (col-major K x N), loaded via ldmatrix.x4 (2 ntiles x 1 kstep per ldsm).

__device__ __forceinline__ void gemm_x(u32 wbase, const u32 (&ah)[8][4], const u32 (&al)[8][4],
                                       bool isHi, float (&d)[16][4], int lane) {
    const u32 off0 = (u32)((((lane & 7) + ((lane >> 4) << 3))) * 256);
    const u32 swz  = (u32)((lane & 7) << 4);
    const u32 kh   = (u32)(((lane >> 3) & 1) * 16);
#pragma unroll
    for (int s = 0; s < 8; s++) {
#pragma unroll
        for (int ntp = 0; ntp < 8; ntp++) {
            u32 r0, r1, r2, r3;
            ldsm4(r0, r1, r2, r3, wbase + off0 + (u32)(ntp * 4096) + (((u32)(32 * s) + kh) ^ swz));
            mma16816(d[2 * ntp],     ah[s], r0, r1);
            mma16816(d[2 * ntp + 1], ah[s], r2, r3);
            if (isHi) {
                mma16816(d[2 * ntp],     al[s], r0, r1);
                mma16816(d[2 * ntp + 1], al[s], r2, r3);
            }
        }
    }
}

__device__ __forceinline__ void gemm_ff(u32 wbase, const char* fr, int kbase,
                                        bool isHi, float (&d)[16][4], int lane) {
    const u32 off0 = (u32)((((lane & 7) + ((lane >> 4) << 3))) * 256);
    const u32 swz  = (u32)((lane & 7) << 4);
    const u32 kh   = (u32)(((lane >> 3) & 1) * 16);
#pragma unroll
    for (int s = 0; s < 8; s++) {
        const int4 q0 = *(const int4*)(fr + ((kbase + s) * 2 + 0) * 512);
        const int4 q1 = *(const int4*)(fr + ((kbase + s) * 2 + 1) * 512);
        u32 ah[4] = {(u32)q0.x, (u32)q1.x, (u32)q0.y, (u32)q1.y};
        u32 al[4] = {(u32)q0.z, (u32)q1.z, (u32)q0.w, (u32)q1.w};
#pragma unroll
        for (int ntp = 0; ntp < 8; ntp++) {
            u32 r0, r1, r2, r3;
            ldsm4(r0, r1, r2, r3, wbase + off0 + (u32)(ntp * 4096) + (((u32)(32 * s) + kh) ^ swz));
            mma16816(d[2 * ntp],     ah, r0, r1);
            mma16816(d[2 * ntp + 1], ah, r2, r3);
            if (isHi) {
                mma16816(d[2 * ntp],     al, r0, r1);
                mma16816(d[2 * ntp + 1], al, r2, r3);
            }
        }
    }
}

__device__ __forceinline__ void zero_d(float (&d)[16][4]) {
#pragma unroll
    for (int i = 0; i < 16; i++)
#pragma unroll
        for (int j = 0; j < 4; j++) d[i][j] = 0.0f;
}

__device__ __forceinline__ void prefetch_sub(u32 ring, u32 mbf, int sub) {
    u32 mb = mbf + 8 * (sub % 3);
    MBARRIER_EXPECT_TX(mb, SUB_BYTES);
    bulk_copy(ring + (sub % 3) * SUB_BYTES, g_wblob + (size_t)sub * SUB_BYTES, SUB_BYTES, mb);
}

// ==================== main kernel ====================

extern __shared__ __align__(16) char smem[];

__global__ void __launch_bounds__(THREADS, 1)
pinn_mma(const float* __restrict__ S,  const float* __restrict__ Tt,
         const float* __restrict__ Bm,
         const float* __restrict__ in_b, const float* __restrict__ b1,
         const float* __restrict__ ow,   const float* __restrict__ ob,
         float* __restrict__ out, int N)
{
    const int tid  = threadIdx.x;
    const int warp = tid >> 5, lane = tid & 31;
    const int grp  = lane >> 2, qc = lane & 3;
    const int base = blockIdx.x * MT;

    const u32 sb   = smem_u32(smem);
    const u32 ring = sb + RING_OFF;
    const u32 mbf  = sb + MBAR_OFF;        // full[3] at +0,8,16
    u32* cnt = (u32*)(smem + MBAR_OFF + 24);    // last-arriver counters [3]
    float* Bs  = (float*)(smem + BOW_OFF);      // 256 floats
    float* ows = Bs + 256;                      // 128 floats
    char*  fr  = smem + FFRAG_OFF + warp * 16384 + lane * 16;  // this thread's frag base

    if (tid == 0) {
        MBARRIER_INIT(mbf + 0,  1);
        MBARRIER_INIT(mbf + 8,  1);
        MBARRIER_INIT(mbf + 16, 1);
        cnt[0] = 0; cnt[1] = 0; cnt[2] = 0;
    }
    __syncthreads();   // barrier/counter init visible before any wait/arrive below

    if (tid == 0) {
        prefetch_sub(ring, mbf, 0);
        prefetch_sub(ring, mbf, 1);
        prefetch_sub(ring, mbf, 2);
    }

    // stage B and out_w
    if (tid < 256) Bs[tid] = Bm[tid];
    if (tid < 128) ows[tid] = ow[tid];

    // this thread's two point rows
    const int r0g = base + warp * 16 + grp;
    const int r1g = r0g + 8;
    const float s0 = (r0g < N) ? S[r0g]  : 0.0f;
    const float t0 = (r0g < N) ? Tt[r0g] : 0.0f;
    const float s1 = (r1g < N) ? S[r1g]  : 0.0f;
    const float t1 = (r1g < N) ? Tt[r1g] : 0.0f;
    __syncthreads();

    // ---- Fourier-feature A fragments -> per-warp smem (overlaps weight copies) ----
    // A[m][k]: k<128 sin(proj[f=k]); k>=128 cos(proj[f=k-128]).
    // kstep t (sin) / t+8 (cos); within kstep, this thread needs f = 16t + {2qc,2qc+1,2qc+8,2qc+9}.
#pragma unroll
    for (int t = 0; t < 8; t++) {
        int f0 = 16 * t + 2 * qc;
        float sn[2][4], cs[2][4];
#pragma unroll
        for (int j = 0; j < 4; j++) {
            int f = f0 + ((j & 1) ? 1 : 0) + ((j & 2) ? 8 : 0);
            float p0 = s0 * Bs[f] + t0 * Bs[128 + f];
            float p1 = s1 * Bs[f] + t1 * Bs[128 + f];
            sn[0][j] = fast_sin(p0);  cs[0][j] = fast_cos(p0);
            sn[1][j] = fast_sin(p1);  cs[1][j] = fast_cos(p1);
        }
        u32 h0, l0, h1, l1, h2, l2, h3, l3;
        // sin -> kstep t
        bf_split2(sn[0][0], sn[0][1], h0, l0);   // a0: row grp,  f0,f0+1
        bf_split2(sn[1][0], sn[1][1], h1, l1);   // a1: row grp+8
        bf_split2(sn[0][2], sn[0][3], h2, l2);   // a2: row grp,  f0+8,f0+9
        bf_split2(sn[1][2], sn[1][3], h3, l3);   // a3
        *(int4*)(fr + (t * 2 + 0) * 512) = make_int4((int)h0, (int)h2, (int)l0, (int)l2);
        *(int4*)(fr + (t * 2 + 1) * 512) = make_int4((int)h1, (int)h3, (int)l1, (int)l3);
        // cos -> kstep t+8
        bf_split2(cs[0][0], cs[0][1], h0, l0);
        bf_split2(cs[1][0], cs[1][1], h1, l1);
        bf_split2(cs[0][2], cs[0][3], h2, l2);
        bf_split2(cs[1][2], cs[1][3], h3, l3);
        *(int4*)(fr + ((t + 8) * 2 + 0) * 512) = make_int4((int)h0, (int)h2, (int)l0, (int)l2);
        *(int4*)(fr + ((t + 8) * 2 + 1) * 512) = make_int4((int)h1, (int)h3, (int)l1, (int)l3);
    }
    // (no sync needed: each thread reads back only its own records)

    // ---- phase stagger: delay warps 4-7 (~epilogue length) so each SMSP's two
    // warps run anti-phase. With last-arriver refill, NO warp blocks on empty,
    // so warp 0 keeps its lead and every SMSP gets a true early/late pair. ----
    if (warp >= 4) {
        u32 c0; asm volatile("mov.u32 %0, %%clock;" : "=r"(c0));
        u32 el = 0;
        do { u32 c; asm volatile("mov.u32 %0, %%clock;" : "=r"(c)); el = c - c0; } while (el < 2600u);
    }

    int sub = 0;
    float d[16][4];
    u32 xh[8][4], xl[8][4];

    // Per-sub protocol (no CTA barriers, no blocking producer):
    //  - each warp: wait full(sub) [acquire], gemm, lane0 atomicAdd on cnt[slot]
    //  - the 8th (last) arriver for this use issues the refill of sub+3.
    //    Its ldsm reads (and everyone else's) are physically complete, so the
    //    overwrite is safe; being the slowest warp, its copy hides in 3-sub slack.
#define DO_SUB(GEMM_CALL) do { \
        MBARRIER_WAIT_PARITY(mbf + 8 * (sub % 3), (sub / 3) & 1); \
        GEMM_CALL; \
        if (lane == 0) { \
            u32 old = atomicAdd(&cnt[sub % 3], 1u); \
            if (old == 8u * (u32)(sub / 3) + 7u && sub + 3 < NSUB) \
                prefetch_sub(ring, mbf, sub + 3); \
        } \
        sub++; \
    } while (0)

#define DO_FF(kbase, isHi) \
    DO_SUB(gemm_ff(ring + (u32)((sub % 3) * SUB_BYTES), fr, (kbase), (isHi), d, lane))
#define DO_X(AH, AL, isHi) \
    DO_SUB(gemm_x(ring + (u32)((sub % 3) * SUB_BYTES), (AH), (AL), (isHi), d, lane))

    // ---- input layer: D = ff @ in_w (K=256), x = sin(OMEGA*(D + in_b)) ----
    zero_d(d);
    DO_FF(0, true);  DO_FF(0, false);
    DO_FF(8, true);  DO_FF(8, false);

#pragma unroll
    for (int s = 0; s < 8; s++) {
#pragma unroll
        for (int p = 0; p < 2; p++) {
            int nt = 2 * s + p;
            int col = 8 * nt + 2 * qc;
            float2 bb = *(const float2*)(in_b + col);
            float v00 = fast_sin(OMEGA * (d[nt][0] + bb.x));
            float v01 = fast_sin(OMEGA * (d[nt][1] + bb.y));
            float v10 = fast_sin(OMEGA * (d[nt][2] + bb.x));
            float v11 = fast_sin(OMEGA * (d[nt][3] + bb.y));
            bf_split2(v00, v01, xh[s][2 * p],     xl[s][2 * p]);
            bf_split2(v10, v11, xh[s][2 * p + 1], xl[s][2 * p + 1]);
        }
    }

    // ---- residual blocks ----
    for (int l = 0; l < 8; l++) {
        const bool skip = ((l & 1) == 0);
        u32 hh[8][4], hl[8][4];

        // GEMM1: D = x @ w1_l ; h = tanh(D + b1_l)
        zero_d(d);
        DO_X(xh, xl, true);  DO_X(xh, xl, false);
#pragma unroll
        for (int s = 0; s < 8; s++) {
#pragma unroll
            for (int p = 0; p < 2; p++) {
                int nt = 2 * s + p;
                int col = 8 * nt + 2 * qc;
                float2 bb = *(const float2*)(b1 + l * 128 + col);
                float v00 = fast_tanh(d[nt][0] + bb.x);
                float v01 = fast_tanh(d[nt][1] + bb.y);
                float v10 = fast_tanh(d[nt][2] + bb.x);
                float v11 = fast_tanh(d[nt][3] + bb.y);
                bf_split2(v00, v01, hh[s][2 * p],     hl[s][2 * p]);
                bf_split2(v10, v11, hh[s][2 * p + 1], hl[s][2 * p + 1]);
            }
        }

        // GEMM2: D = h @ w2_l (+ ff @ skip_w[l/2])
        zero_d(d);
        DO_X(hh, hl, true);  DO_X(hh, hl, false);
        if (skip) {
            DO_FF(0, true);  DO_FF(0, false);
            DO_FF(8, true);  DO_FF(8, false);
        }

        // epilogue2: x = x + D + b2c (precombined b2 + skb); re-split into frags
#pragma unroll
        for (int s = 0; s < 8; s++) {
#pragma unroll
            for (int p = 0; p < 2; p++) {
                int nt = 2 * s + p;
                int col = 8 * nt + 2 * qc;
                float2 bb = *(const float2*)(g_b2c + l * 128 + col);
                int i0 = 2 * p, i1 = 2 * p + 1;
                float v00 = bflo(xh[s][i0]) + bflo(xl[s][i0]) + d[nt][0] + bb.x;
                float v01 = bfhi(xh[s][i0]) + bfhi(xl[s][i0]) + d[nt][1] + bb.y;
                float v10 = bflo(xh[s][i1]) + bflo(xl[s][i1]) + d[nt][2] + bb.x;
                float v11 = bfhi(xh[s][i1]) + bfhi(xl[s][i1]) + d[nt][3] + bb.y;
                bf_split2(v00, v01, xh[s][i0], xl[s][i0]);
                bf_split2(v10, v11, xh[s][i1], xl[s][i1]);
            }
        }
    }

    // ---- output layer: out = x @ out_w + out_b ----
    float a0 = 0.0f, a1 = 0.0f;
#pragma unroll
    for (int s = 0; s < 8; s++) {
#pragma unroll
        for (int p = 0; p < 2; p++) {
            int nt = 2 * s + p;
            int col = 8 * nt + 2 * qc;
            float w0 = ows[col], w1v = ows[col + 1];
            int i0 = 2 * p, i1 = 2 * p + 1;
            a0 += (bflo(xh[s][i0]) + bflo(xl[s][i0])) * w0
                + (bfhi(xh[s][i0]) + bfhi(xl[s][i0])) * w1v;
            a1 += (bflo(xh[s][i1]) + bflo(xl[s][i1])) * w0
                + (bfhi(xh[s][i1]) + bfhi(xl[s][i1])) * w1v;
        }
    }
    a0 += __shfl_xor_sync(0xFFFFFFFF, a0, 1);
    a0 += __shfl_xor_sync(0xFFFFFFFF, a0, 2);
    a1 += __shfl_xor_sync(0xFFFFFFFF, a1, 1);
    a1 += __shfl_xor_sync(0xFFFFFFFF, a1, 2);
    if (qc == 0) {
        float obv = ob[0];
        if (r0g < N) out[r0g] = a0 + obv;
        if (r1g < N) out[r1g] = a1 + obv;
    }
#undef DO_FF
#undef DO_X
#undef DO_SUB
}

// ==================== launcher ====================

extern "C" void kernel_launch(void* const* d_in, const int* in_sizes, int n_in,
                              void* d_out, int out_size) {
    const float* S    = (const float*)d_in[0];
    const float* T    = (const float*)d_in[1];
    const float* B    = (const float*)d_in[2];
    const float* in_w = (const float*)d_in[3];
    const float* in_b = (const float*)d_in[4];
    const float* w1   = (const float*)d_in[5];
    const float* b1   = (const float*)d_in[6];
    const float* w2   = (const float*)d_in[7];
    const float* b2   = (const float*)d_in[8];
    const float* skw  = (const float*)d_in[9];
    const float* skb  = (const float*)d_in[10];
    const float* ow   = (const float*)d_in[11];
    const float* ob   = (const float*)d_in[12];
    float* out        = (float*)d_out;

    int N = in_sizes[0];

    convert_weights<<<(26 * 16384 + 255) / 256, 256>>>(in_w, w1, w2, skw, b2, skb);

    cudaFuncSetAttribute(pinn_mma, cudaFuncAttributeMaxDynamicSharedMemorySize, SMEM_BYTES);
    int grid = (N + MT - 1) / MT;
    pinn_mma<<<grid, THREADS, SMEM_BYTES>>>(S, T, B, in_b, b1, ow, ob, out, N);
}